// round 11
// baseline (speedup 1.0000x reference)
#include <cuda_runtime.h>
#include <cuda_fp16.h>
#include <cstdint>
#include <math.h>

#define B_N   16384
#define K_N   50
#define V_N   100000
#define BK_N  (B_N * K_N)          // 819200
#define NTILE (BK_N / 128)         // 6400 tiles of 128 pairs
#define VTILE (V_N / 16)           // 6250 vocab warp-tiles

typedef unsigned int u32;

// ---------------------------------------------------------------------------
// Device scratch (static — no cudaMalloc allowed)
// ---------------------------------------------------------------------------
__device__ float g_P  [(size_t)V_N * 64];      // u2e @ w1_W[0:64,:]
__device__ float g_A1B[(size_t)V_N * 64];      // u2e @ a1_W[64:128,:]
__device__ u32   g_O16[(size_t)BK_N * 32];     // o_history (fp16x2) 105MB
__device__ float g_S  [(size_t)BK_N];          // attention scores
// fp16 B fragments: [L:5][kt:4][nt:8][lane:32][reg:2] u32 (fp16x2)
// L: 0=w2W  1=a1W[0:64]  2=a2W  3=w1W[0:64]  4=a1W[64:128]
__device__ u32   g_Wf [5 * 2048];              // 40KB

// ---------------------------------------------------------------------------
// fp16 helpers
// ---------------------------------------------------------------------------
__device__ __forceinline__ u32 pack_h2(float v0, float v1) {
    __half2 h = __floats2half2_rn(v0, v1);
    return *reinterpret_cast<u32*>(&h);
}
__device__ __forceinline__ void split2h(float v0, float v1, u32& h, u32& l) {
    const __half2 hh = __floats2half2_rn(v0, v1);
    h = *reinterpret_cast<const u32*>(&hh);
    const float2 hf = __half22float2(hh);
    const __half2 ll = __floats2half2_rn(v0 - hf.x, v1 - hf.y);
    l = *reinterpret_cast<const u32*>(&ll);
}
// m16n8k16 row.col fp16 MMA, fp32 accumulate (sm_80+ baseline)
__device__ __forceinline__ void mma16816(float& d0, float& d1, float& d2, float& d3,
                                         u32 a0, u32 a1, u32 a2, u32 a3,
                                         u32 b0, u32 b1) {
    asm("mma.sync.aligned.m16n8k16.row.col.f32.f16.f16.f32 "
        "{%0,%1,%2,%3}, {%4,%5,%6,%7}, {%8,%9}, {%0,%1,%2,%3};"
        : "+f"(d0), "+f"(d1), "+f"(d2), "+f"(d3)
        : "r"(a0), "r"(a1), "r"(a2), "r"(a3), "r"(b0), "r"(b1));
}

// ---------------------------------------------------------------------------
// Kernel 0: fp16 B-fragments, 5 matrices.
// ---------------------------------------------------------------------------
__global__ void __launch_bounds__(256) k_wfrag(const float* __restrict__ w2W,
                                               const float* __restrict__ a1W,
                                               const float* __restrict__ a2W,
                                               const float* __restrict__ w1W)
{
    const int idx = blockIdx.x * 256 + threadIdx.x;   // 5*4*8*32 = 5120
    if (idx >= 5120) return;
    const int lane = idx & 31;
    const int nt   = (idx >> 5) & 7;
    const int kt   = (idx >> 8) & 3;
    const int L    = idx >> 10;

    const float* W;
    if (L == 0)      W = w2W;
    else if (L == 1) W = a1W;
    else if (L == 2) W = a2W;
    else if (L == 3) W = w1W;
    else             W = a1W + 4096;    // rows 64..127

    const int n  = nt * 8 + (lane >> 2);
    const int k0 = kt * 16 + (lane & 3) * 2;

    const int f = L * 2048 + ((kt*8 + nt)*32 + lane)*2;
    g_Wf[f]     = pack_h2(W[k0*64+n],     W[(k0+1)*64+n]);
    g_Wf[f + 1] = pack_h2(W[(k0+8)*64+n], W[(k0+9)*64+n]);
}

// ---------------------------------------------------------------------------
// Single-tile 64->64 GEMM (M=16): 2-term fp16 split — k_pre only.
// ---------------------------------------------------------------------------
__device__ __forceinline__ void gemm64(float* D, const u32* ah, const u32* al,
                                       const u32* sBFL, int lane)
{
    #pragma unroll
    for (int nt = 0; nt < 8; nt++) {
        float d0=0.f,d1=0.f,d2=0.f,d3=0.f;
        #pragma unroll
        for (int kt = 0; kt < 4; kt++) {
            const uint2 b = *reinterpret_cast<const uint2*>(sBFL + (kt*8 + nt)*64 + lane*2);
            mma16816(d0,d1,d2,d3, ah[kt*4],ah[kt*4+1],ah[kt*4+2],ah[kt*4+3], b.x,b.y);
            mma16816(d0,d1,d2,d3, al[kt*4],al[kt*4+1],al[kt*4+2],al[kt*4+3], b.x,b.y);
        }
        D[nt*4+0]=d0; D[nt*4+1]=d1; D[nt*4+2]=d2; D[nt*4+3]=d3;
    }
}

// Dual-tile (M=32), single-term A: all k_main layers.
__device__ __forceinline__ void gemm64x2_1t(float* D,
                                            const u32* ahA, const u32* ahB,
                                            const u32* sBFL, int lane)
{
    #pragma unroll
    for (int nt = 0; nt < 8; nt++) {
        float d0=0.f,d1=0.f,d2=0.f,d3=0.f,d4=0.f,d5=0.f,d6=0.f,d7=0.f;
        #pragma unroll
        for (int kt = 0; kt < 4; kt++) {
            const uint2 b = *reinterpret_cast<const uint2*>(sBFL + (kt*8 + nt)*64 + lane*2);
            mma16816(d0,d1,d2,d3, ahA[kt*4],ahA[kt*4+1],ahA[kt*4+2],ahA[kt*4+3], b.x,b.y);
            mma16816(d4,d5,d6,d7, ahB[kt*4],ahB[kt*4+1],ahB[kt*4+2],ahB[kt*4+3], b.x,b.y);
        }
        D[nt*8+0]=d0; D[nt*8+1]=d1; D[nt*8+2]=d2; D[nt*8+3]=d3;
        D[nt*8+4]=d4; D[nt*8+5]=d5; D[nt*8+6]=d6; D[nt*8+7]=d7;
    }
}

// ---------------------------------------------------------------------------
// Kernel 1: HMMA per-vocab precompute of P and A1B (2-term, accurate tables).
// ---------------------------------------------------------------------------
__global__ void __launch_bounds__(256) k_pre(const float* __restrict__ u2e)
{
    __shared__ u32 sBF[4096];

    const int tid = threadIdx.x;
    {
        const uint4* src = reinterpret_cast<const uint4*>(g_Wf + 3 * 2048);
        uint4* dst = reinterpret_cast<uint4*>(sBF);
        for (int i = tid; i < 1024; i += 256) dst[i] = src[i];
    }
    __syncthreads();

    const int wid  = tid >> 5;
    const int lane = tid & 31;
    const int g    = lane >> 2;
    const int q2   = (lane & 3) << 1;

    const int wt = blockIdx.x * 8 + wid;
    if (wt >= VTILE) return;
    const int v0 = wt * 16 + g;
    const int v1 = v0 + 8;

    u32 ah[16], al[16];
    #pragma unroll
    for (int rr = 0; rr < 2; rr++) {
        const float* Mr = u2e + (size_t)(wt*16 + g + rr*8) * 64;
        #pragma unroll
        for (int kt = 0; kt < 4; kt++) {
            const int c0 = kt*16 + q2;
            const float2 pa = *reinterpret_cast<const float2*>(Mr + c0);
            const float2 pb = *reinterpret_cast<const float2*>(Mr + c0 + 8);
            split2h(pa.x, pa.y, ah[kt*4 + rr],     al[kt*4 + rr]);
            split2h(pb.x, pb.y, ah[kt*4 + 2 + rr], al[kt*4 + 2 + rr]);
        }
    }

    float D[32];
    gemm64(D, ah, al, sBF, lane);
    #pragma unroll
    for (int nt = 0; nt < 8; nt++) {
        const int c0 = nt*8 + q2;
        *reinterpret_cast<float2*>(g_P + (size_t)v0*64 + c0) = make_float2(D[nt*4+0], D[nt*4+1]);
        *reinterpret_cast<float2*>(g_P + (size_t)v1*64 + c0) = make_float2(D[nt*4+2], D[nt*4+3]);
    }
    gemm64(D, ah, al, sBF + 2048, lane);
    #pragma unroll
    for (int nt = 0; nt < 8; nt++) {
        const int c0 = nt*8 + q2;
        *reinterpret_cast<float2*>(g_A1B + (size_t)v0*64 + c0) = make_float2(D[nt*4+0], D[nt*4+1]);
        *reinterpret_cast<float2*>(g_A1B + (size_t)v1*64 + c0) = make_float2(D[nt*4+2], D[nt*4+3]);
    }
}

// ---------------------------------------------------------------------------
// Main kernel: layers 1..4 + scores, single-term fp16 throughout.
// Each warp: 32 pairs (two m16 tiles). Block = 4 warps = 128 pairs.
// ---------------------------------------------------------------------------
#define DSM_U32  (6144 + 512 + 5*64)   // 6976 u32 = 27904 B
#define DSM_BYTES (DSM_U32 * 4)

__global__ void __launch_bounds__(128, 2) k_main(
    const int*   __restrict__ nodes,
    const int*   __restrict__ nidx,
    const float* __restrict__ labels,
    const float* __restrict__ w1W,
    const float* __restrict__ w1b,
    const float* __restrict__ w2b,
    const float* __restrict__ a1b,
    const float* __restrict__ a2b,
    const float* __restrict__ a3W,
    const float* __restrict__ a3b)
{
    extern __shared__ u32 dsm[];
    u32*   sBF  = dsm;                       // 6144 u32 (24KB): L=0,1,2
    float* sW1L = (float*)(dsm + 6144);      // 512
    float* sB1  = sW1L + 512;
    float* sB2  = sB1 + 64;
    float* sBa1 = sB2 + 64;
    float* sBa2 = sBa1 + 64;
    float* sA3  = sBa2 + 64;

    const int tid = threadIdx.x;
    {
        const uint4* src = reinterpret_cast<const uint4*>(g_Wf);
        uint4* dst = reinterpret_cast<uint4*>(sBF);
        for (int i = tid; i < 1536; i += 128) dst[i] = src[i];
        for (int i = tid; i < 512; i += 128) sW1L[i] = w1W[4096 + i];
        if (tid < 64) {
            sB1 [tid] = w1b[tid];
            sB2 [tid] = w2b[tid];
            sBa1[tid] = a1b[tid];
            sBa2[tid] = a2b[tid];
            sA3 [tid] = a3W[tid];
        }
    }
    __syncthreads();

    const float a3b0 = a3b[0];
    const int wid  = tid >> 5;             // 0..3
    const int lane = tid & 31;
    const int g    = lane >> 2;            // 0..7
    const int q2   = (lane & 3) << 1;      // 0,2,4,6

    for (int t = blockIdx.x; t < NTILE; t += gridDim.x) {
        const int pb = t * 128 + wid * 32 + g;   // rows pb, pb+8, pb+16, pb+24

        u32 ahA[16], ahB[16];

        // ============ LAYER 1 (scalar) → A fragments (hi only) ============
        #pragma unroll
        for (int rr = 0; rr < 4; rr++) {
            const int p  = pb + rr * 8;
            u32* ah = (rr < 2) ? ahA : ahB;
            const int sl = rr & 1;

            const int ni = __ldg(&nidx[p]);
            const float* Pr = g_P + (size_t)ni * 64;
            const float4* lv = reinterpret_cast<const float4*>(labels + (size_t)p * 8);
            const float4 la = lv[0], lb = lv[1];
            const float lab[8] = { la.x, la.y, la.z, la.w, lb.x, lb.y, lb.z, lb.w };

            #pragma unroll
            for (int kt = 0; kt < 4; kt++) {
                const int c0 = kt * 16 + q2;
                const float2 pa = *reinterpret_cast<const float2*>(Pr + c0);
                const float2 pbv = *reinterpret_cast<const float2*>(Pr + c0 + 8);
                float v0 = pa.x + sB1[c0];
                float v1 = pa.y + sB1[c0 + 1];
                float v2 = pbv.x + sB1[c0 + 8];
                float v3 = pbv.y + sB1[c0 + 9];
                #pragma unroll
                for (int j = 0; j < 8; j++) {
                    const float* wr = sW1L + j * 64 + c0;
                    v0 = fmaf(lab[j], wr[0], v0);
                    v1 = fmaf(lab[j], wr[1], v1);
                    v2 = fmaf(lab[j], wr[8], v2);
                    v3 = fmaf(lab[j], wr[9], v3);
                }
                ah[kt*4 + sl]     = pack_h2(fmaxf(v0, 0.f), fmaxf(v1, 0.f));
                ah[kt*4 + 2 + sl] = pack_h2(fmaxf(v2, 0.f), fmaxf(v3, 0.f));
            }
        }

        float D[64];

        // ================= LAYER 2: o = relu(h @ W2 + b2) =================
        gemm64x2_1t(D, ahA, ahB, sBF, lane);
        #pragma unroll
        for (int nt = 0; nt < 8; nt++) {
            const int c0 = nt * 8 + q2;
            const int cp = nt * 4 + (lane & 3);      // half2 column-pair index
            const int kt = nt >> 1, hf = nt & 1;
            #pragma unroll
            for (int half = 0; half < 2; half++) {
                const float b0 = sB2[c0], b1 = sB2[c0 + 1];
                const float v0 = fmaxf(D[nt*8 + half*4 + 0] + b0, 0.f);
                const float v1 = fmaxf(D[nt*8 + half*4 + 1] + b1, 0.f);
                const float v2 = fmaxf(D[nt*8 + half*4 + 2] + b0, 0.f);
                const float v3 = fmaxf(D[nt*8 + half*4 + 3] + b1, 0.f);
                const int r0 = pb + half * 16;
                const u32 p01 = pack_h2(v0, v1);
                const u32 p23 = pack_h2(v2, v3);
                g_O16[(size_t)r0 * 32 + cp]       = p01;
                g_O16[(size_t)(r0 + 8) * 32 + cp] = p23;
                u32* ah = half ? ahB : ahA;
                ah[kt*4 + hf*2 + 0] = p01;
                ah[kt*4 + hf*2 + 1] = p23;
            }
        }

        // ===== LAYER 3: a = relu(o @ A1a + A1B[node] + b) (scores only) ===
        const float* G[4];
        #pragma unroll
        for (int rr = 0; rr < 4; rr++)
            G[rr] = g_A1B + (size_t)__ldg(&nodes[(pb + rr * 8) / K_N]) * 64;

        gemm64x2_1t(D, ahA, ahB, sBF + 2048, lane);
        #pragma unroll
        for (int nt = 0; nt < 8; nt++) {
            const int c0 = nt * 8 + q2;
            const int kt = nt >> 1, hf = nt & 1;
            #pragma unroll
            for (int half = 0; half < 2; half++) {
                const float2 g0 = *reinterpret_cast<const float2*>(G[half*2]     + c0);
                const float2 g1 = *reinterpret_cast<const float2*>(G[half*2 + 1] + c0);
                const float b0 = sBa1[c0], b1 = sBa1[c0 + 1];
                const float v0 = fmaxf(D[nt*8 + half*4 + 0] + b0 + g0.x, 0.f);
                const float v1 = fmaxf(D[nt*8 + half*4 + 1] + b1 + g0.y, 0.f);
                const float v2 = fmaxf(D[nt*8 + half*4 + 2] + b0 + g1.x, 0.f);
                const float v3 = fmaxf(D[nt*8 + half*4 + 3] + b1 + g1.y, 0.f);
                u32* ah = half ? ahB : ahA;
                ah[kt*4 + hf*2 + 0] = pack_h2(v0, v1);
                ah[kt*4 + hf*2 + 1] = pack_h2(v2, v3);
            }
        }

        // ========= LAYER 4: a2 = relu(a @ A2 + b); score = a2 . a3 ========
        gemm64x2_1t(D, ahA, ahB, sBF + 4096, lane);
        float s[4] = {0.f, 0.f, 0.f, 0.f};
        #pragma unroll
        for (int nt = 0; nt < 8; nt++) {
            const int c0 = nt * 8 + q2;
            const float b0 = sBa2[c0], b1 = sBa2[c0 + 1];
            const float w0 = sA3[c0],  w1 = sA3[c0 + 1];
            #pragma unroll
            for (int half = 0; half < 2; half++) {
                const float v0 = fmaxf(D[nt*8 + half*4 + 0] + b0, 0.f);
                const float v1 = fmaxf(D[nt*8 + half*4 + 1] + b1, 0.f);
                const float v2 = fmaxf(D[nt*8 + half*4 + 2] + b0, 0.f);
                const float v3 = fmaxf(D[nt*8 + half*4 + 3] + b1, 0.f);
                s[half*2]     = fmaf(v0, w0, fmaf(v1, w1, s[half*2]));
                s[half*2 + 1] = fmaf(v2, w0, fmaf(v3, w1, s[half*2 + 1]));
            }
        }
        #pragma unroll
        for (int rr = 0; rr < 4; rr++) {
            float sv = s[rr];
            sv += __shfl_xor_sync(0xffffffffu, sv, 1);
            sv += __shfl_xor_sync(0xffffffffu, sv, 2);
            if ((lane & 3) == 0) g_S[pb + rr * 8] = sv + a3b0;
        }
    }
}

// ---------------------------------------------------------------------------
// Kernel 3: masked softmax + aggregate (R7 proven structure, fp16 o reads).
// ---------------------------------------------------------------------------
__global__ void __launch_bounds__(256) k_agg(const int*   __restrict__ nodes,
                                             const int*   __restrict__ nlen,
                                             const float* __restrict__ u2e,
                                             float*       __restrict__ out)
{
    const int wid  = (blockIdx.x * 256 + threadIdx.x) >> 5;
    const int lane = threadIdx.x & 31;
    if (wid >= B_N) return;
    const int b   = wid;
    const int len = nlen[b];

    if (len <= 0) {
        const int node = nodes[b];
        const float2* src = reinterpret_cast<const float2*>(u2e + (size_t)node * 64);
        reinterpret_cast<float2*>(out + (size_t)b * 64)[lane] = src[lane];
        return;
    }

    const float* Sb = g_S + (size_t)b * K_N;
    float s0 = (lane      < len) ? Sb[lane]      : -3.0e38f;
    float s1 = (lane + 32 < len) ? Sb[lane + 32] : -3.0e38f;

    float m = fmaxf(s0, s1);
    #pragma unroll
    for (int o = 16; o > 0; o >>= 1) m = fmaxf(m, __shfl_xor_sync(0xffffffffu, m, o));

    const float e0 = (lane      < len) ? expf(s0 - m) : 0.f;
    const float e1 = (lane + 32 < len) ? expf(s1 - m) : 0.f;

    float ss = e0 + e1;
    #pragma unroll
    for (int o = 16; o > 0; o >>= 1) ss += __shfl_xor_sync(0xffffffffu, ss, o);

    const float inv = 1.f / ss;
    const float w0 = e0 * inv;
    const float w1 = e1 * inv;

    float2 agg = make_float2(0.f, 0.f);
    const u32* Ob = g_O16 + (size_t)b * K_N * 32;
    for (int k = 0; k < len; k++) {
        const float ak = (k < 32) ? __shfl_sync(0xffffffffu, w0, k)
                                  : __shfl_sync(0xffffffffu, w1, k - 32);
        const u32 ov = Ob[k * 32 + lane];
        const float2 of = __half22float2(*reinterpret_cast<const __half2*>(&ov));
        agg.x = fmaf(ak, of.x, agg.x);
        agg.y = fmaf(ak, of.y, agg.y);
    }
    reinterpret_cast<float2*>(out + (size_t)b * 64)[lane] = agg;
}

// ---------------------------------------------------------------------------
// kernel_launch
// ---------------------------------------------------------------------------
extern "C" void kernel_launch(void* const* d_in, const int* in_sizes, int n_in,
                              void* d_out, int out_size)
{
    const int*   nodes  = (const int*)  d_in[0];
    const int*   nidx   = (const int*)  d_in[1];
    const int*   nlen   = (const int*)  d_in[2];
    const float* labels = (const float*)d_in[3];
    const float* u2e    = (const float*)d_in[4];
    const float* w1W    = (const float*)d_in[5];
    const float* w1b    = (const float*)d_in[6];
    const float* w2W    = (const float*)d_in[7];
    const float* w2b    = (const float*)d_in[8];
    const float* a1W    = (const float*)d_in[9];
    const float* a1b    = (const float*)d_in[10];
    const float* a2W    = (const float*)d_in[11];
    const float* a2b    = (const float*)d_in[12];
    const float* a3W    = (const float*)d_in[13];
    const float* a3b    = (const float*)d_in[14];
    float* out = (float*)d_out;

    cudaFuncSetAttribute(k_main, cudaFuncAttributeMaxDynamicSharedMemorySize, DSM_BYTES);

    k_wfrag<<<20, 256>>>(w2W, a1W, a2W, w1W);
    k_pre  <<<(VTILE + 7) / 8, 256>>>(u2e);
    k_main <<<296, 128, DSM_BYTES>>>(nodes, nidx, labels, w1W, w1b,
                                     w2b, a1b, a2b, a3W, a3b);
    k_agg  <<<(B_N * 32 + 255) / 256, 256>>>(nodes, nlen, u2e, out);
}

// round 12
// speedup vs baseline: 1.4570x; 1.4570x over previous
#include <cuda_runtime.h>
#include <cuda_fp16.h>
#include <cstdint>
#include <math.h>

#define B_N   16384
#define K_N   50
#define V_N   100000
#define BK_N  (B_N * K_N)          // 819200
#define NTILE (BK_N / 128)         // 6400 tiles of 128 pairs
#define VTILE (V_N / 16)           // 6250 vocab warp-tiles

typedef unsigned int u32;

// ---------------------------------------------------------------------------
// Device scratch (static — no cudaMalloc allowed)
// ---------------------------------------------------------------------------
__device__ float g_P  [(size_t)V_N * 64];      // u2e @ w1_W[0:64,:]
__device__ float g_A1B[(size_t)V_N * 64];      // u2e @ a1_W[64:128,:]
// o_history fp16x2: row = pair, 32 u32/row; slot (l4*8 + nt) holds cols nt*8+l4*2+{0,1}
__device__ u32   g_O16[(size_t)BK_N * 32];     // 105MB
__device__ float g_S  [(size_t)BK_N];          // attention scores
// fp16 B fragments: [L:5][kt:4][nt:8][lane:32][reg:2] u32 (fp16x2)
// L: 0=w2W  1=a1W[0:64]  2=a2W  3=w1W[0:64]  4=a1W[64:128]
__device__ u32   g_Wf [5 * 2048];              // 40KB

// ---------------------------------------------------------------------------
// fp16 helpers
// ---------------------------------------------------------------------------
__device__ __forceinline__ u32 pack_h2(float v0, float v1) {
    __half2 h = __floats2half2_rn(v0, v1);
    return *reinterpret_cast<u32*>(&h);
}
__device__ __forceinline__ void split2h(float v0, float v1, u32& h, u32& l) {
    const __half2 hh = __floats2half2_rn(v0, v1);
    h = *reinterpret_cast<const u32*>(&hh);
    const float2 hf = __half22float2(hh);
    const __half2 ll = __floats2half2_rn(v0 - hf.x, v1 - hf.y);
    l = *reinterpret_cast<const u32*>(&ll);
}
// m16n8k16 row.col fp16 MMA, fp32 accumulate (sm_80+ baseline)
__device__ __forceinline__ void mma16816(float& d0, float& d1, float& d2, float& d3,
                                         u32 a0, u32 a1, u32 a2, u32 a3,
                                         u32 b0, u32 b1) {
    asm("mma.sync.aligned.m16n8k16.row.col.f32.f16.f16.f32 "
        "{%0,%1,%2,%3}, {%4,%5,%6,%7}, {%8,%9}, {%0,%1,%2,%3};"
        : "+f"(d0), "+f"(d1), "+f"(d2), "+f"(d3)
        : "r"(a0), "r"(a1), "r"(a2), "r"(a3), "r"(b0), "r"(b1));
}

// ---------------------------------------------------------------------------
// Kernel 0: fp16 B-fragments, 5 matrices.
// ---------------------------------------------------------------------------
__global__ void __launch_bounds__(256) k_wfrag(const float* __restrict__ w2W,
                                               const float* __restrict__ a1W,
                                               const float* __restrict__ a2W,
                                               const float* __restrict__ w1W)
{
    const int idx = blockIdx.x * 256 + threadIdx.x;   // 5*4*8*32 = 5120
    if (idx >= 5120) return;
    const int lane = idx & 31;
    const int nt   = (idx >> 5) & 7;
    const int kt   = (idx >> 8) & 3;
    const int L    = idx >> 10;

    const float* W;
    if (L == 0)      W = w2W;
    else if (L == 1) W = a1W;
    else if (L == 2) W = a2W;
    else if (L == 3) W = w1W;
    else             W = a1W + 4096;    // rows 64..127

    const int n  = nt * 8 + (lane >> 2);
    const int k0 = kt * 16 + (lane & 3) * 2;

    const int f = L * 2048 + ((kt*8 + nt)*32 + lane)*2;
    g_Wf[f]     = pack_h2(W[k0*64+n],     W[(k0+1)*64+n]);
    g_Wf[f + 1] = pack_h2(W[(k0+8)*64+n], W[(k0+9)*64+n]);
}

// ---------------------------------------------------------------------------
// Single-tile 64->64 GEMM (M=16): 2-term fp16 split — k_pre only.
// ---------------------------------------------------------------------------
__device__ __forceinline__ void gemm64(float* D, const u32* ah, const u32* al,
                                       const u32* sBFL, int lane)
{
    #pragma unroll
    for (int nt = 0; nt < 8; nt++) {
        float d0=0.f,d1=0.f,d2=0.f,d3=0.f;
        #pragma unroll
        for (int kt = 0; kt < 4; kt++) {
            const uint2 b = *reinterpret_cast<const uint2*>(sBFL + (kt*8 + nt)*64 + lane*2);
            mma16816(d0,d1,d2,d3, ah[kt*4],ah[kt*4+1],ah[kt*4+2],ah[kt*4+3], b.x,b.y);
            mma16816(d0,d1,d2,d3, al[kt*4],al[kt*4+1],al[kt*4+2],al[kt*4+3], b.x,b.y);
        }
        D[nt*4+0]=d0; D[nt*4+1]=d1; D[nt*4+2]=d2; D[nt*4+3]=d3;
    }
}

// Dual-tile (M=32), single-term A: all k_main layers.
__device__ __forceinline__ void gemm64x2_1t(float* D,
                                            const u32* ahA, const u32* ahB,
                                            const u32* sBFL, int lane)
{
    #pragma unroll
    for (int nt = 0; nt < 8; nt++) {
        float d0=0.f,d1=0.f,d2=0.f,d3=0.f,d4=0.f,d5=0.f,d6=0.f,d7=0.f;
        #pragma unroll
        for (int kt = 0; kt < 4; kt++) {
            const uint2 b = *reinterpret_cast<const uint2*>(sBFL + (kt*8 + nt)*64 + lane*2);
            mma16816(d0,d1,d2,d3, ahA[kt*4],ahA[kt*4+1],ahA[kt*4+2],ahA[kt*4+3], b.x,b.y);
            mma16816(d4,d5,d6,d7, ahB[kt*4],ahB[kt*4+1],ahB[kt*4+2],ahB[kt*4+3], b.x,b.y);
        }
        D[nt*8+0]=d0; D[nt*8+1]=d1; D[nt*8+2]=d2; D[nt*8+3]=d3;
        D[nt*8+4]=d4; D[nt*8+5]=d5; D[nt*8+6]=d6; D[nt*8+7]=d7;
    }
}

// ---------------------------------------------------------------------------
// Kernel 1: HMMA per-vocab precompute of P and A1B (2-term, accurate tables).
// ---------------------------------------------------------------------------
__global__ void __launch_bounds__(256) k_pre(const float* __restrict__ u2e)
{
    __shared__ u32 sBF[4096];

    const int tid = threadIdx.x;
    {
        const uint4* src = reinterpret_cast<const uint4*>(g_Wf + 3 * 2048);
        uint4* dst = reinterpret_cast<uint4*>(sBF);
        for (int i = tid; i < 1024; i += 256) dst[i] = src[i];
    }
    __syncthreads();

    const int wid  = tid >> 5;
    const int lane = tid & 31;
    const int g    = lane >> 2;
    const int q2   = (lane & 3) << 1;

    const int wt = blockIdx.x * 8 + wid;
    if (wt >= VTILE) return;
    const int v0 = wt * 16 + g;
    const int v1 = v0 + 8;

    u32 ah[16], al[16];
    #pragma unroll
    for (int rr = 0; rr < 2; rr++) {
        const float* Mr = u2e + (size_t)(wt*16 + g + rr*8) * 64;
        #pragma unroll
        for (int kt = 0; kt < 4; kt++) {
            const int c0 = kt*16 + q2;
            const float2 pa = *reinterpret_cast<const float2*>(Mr + c0);
            const float2 pb = *reinterpret_cast<const float2*>(Mr + c0 + 8);
            split2h(pa.x, pa.y, ah[kt*4 + rr],     al[kt*4 + rr]);
            split2h(pb.x, pb.y, ah[kt*4 + 2 + rr], al[kt*4 + 2 + rr]);
        }
    }

    float D[32];
    gemm64(D, ah, al, sBF, lane);
    #pragma unroll
    for (int nt = 0; nt < 8; nt++) {
        const int c0 = nt*8 + q2;
        *reinterpret_cast<float2*>(g_P + (size_t)v0*64 + c0) = make_float2(D[nt*4+0], D[nt*4+1]);
        *reinterpret_cast<float2*>(g_P + (size_t)v1*64 + c0) = make_float2(D[nt*4+2], D[nt*4+3]);
    }
    gemm64(D, ah, al, sBF + 2048, lane);
    #pragma unroll
    for (int nt = 0; nt < 8; nt++) {
        const int c0 = nt*8 + q2;
        *reinterpret_cast<float2*>(g_A1B + (size_t)v0*64 + c0) = make_float2(D[nt*4+0], D[nt*4+1]);
        *reinterpret_cast<float2*>(g_A1B + (size_t)v1*64 + c0) = make_float2(D[nt*4+2], D[nt*4+3]);
    }
}

// ---------------------------------------------------------------------------
// Main kernel: layers 1..4 + scores, single-term fp16 throughout.
// Each warp: 32 pairs. Coalesced 128B-row fp16 o stores.
// ---------------------------------------------------------------------------
#define DSM_U32  (6144 + 512 + 5*64)   // 6976 u32 = 27904 B
#define DSM_BYTES (DSM_U32 * 4)

__global__ void __launch_bounds__(128, 2) k_main(
    const int*   __restrict__ nodes,
    const int*   __restrict__ nidx,
    const float* __restrict__ labels,
    const float* __restrict__ w1W,
    const float* __restrict__ w1b,
    const float* __restrict__ w2b,
    const float* __restrict__ a1b,
    const float* __restrict__ a2b,
    const float* __restrict__ a3W,
    const float* __restrict__ a3b)
{
    extern __shared__ u32 dsm[];
    u32*   sBF  = dsm;                       // 6144 u32 (24KB): L=0,1,2
    float* sW1L = (float*)(dsm + 6144);      // 512
    float* sB1  = sW1L + 512;
    float* sB2  = sB1 + 64;
    float* sBa1 = sB2 + 64;
    float* sBa2 = sBa1 + 64;
    float* sA3  = sBa2 + 64;

    const int tid = threadIdx.x;
    {
        const uint4* src = reinterpret_cast<const uint4*>(g_Wf);
        uint4* dst = reinterpret_cast<uint4*>(sBF);
        for (int i = tid; i < 1536; i += 128) dst[i] = src[i];
        for (int i = tid; i < 512; i += 128) sW1L[i] = w1W[4096 + i];
        if (tid < 64) {
            sB1 [tid] = w1b[tid];
            sB2 [tid] = w2b[tid];
            sBa1[tid] = a1b[tid];
            sBa2[tid] = a2b[tid];
            sA3 [tid] = a3W[tid];
        }
    }
    __syncthreads();

    const float a3b0 = a3b[0];
    const int wid  = tid >> 5;             // 0..3
    const int lane = tid & 31;
    const int g    = lane >> 2;            // 0..7
    const int q2   = (lane & 3) << 1;      // 0,2,4,6

    for (int t = blockIdx.x; t < NTILE; t += gridDim.x) {
        const int pb = t * 128 + wid * 32 + g;   // rows pb, pb+8, pb+16, pb+24

        u32 ahA[16], ahB[16];

        // ============ LAYER 1 (scalar) → A fragments (hi only) ============
        #pragma unroll
        for (int rr = 0; rr < 4; rr++) {
            const int p  = pb + rr * 8;
            u32* ah = (rr < 2) ? ahA : ahB;
            const int sl = rr & 1;

            const int ni = __ldg(&nidx[p]);
            const float* Pr = g_P + (size_t)ni * 64;
            const float4* lv = reinterpret_cast<const float4*>(labels + (size_t)p * 8);
            const float4 la = lv[0], lb = lv[1];
            const float lab[8] = { la.x, la.y, la.z, la.w, lb.x, lb.y, lb.z, lb.w };

            #pragma unroll
            for (int kt = 0; kt < 4; kt++) {
                const int c0 = kt * 16 + q2;
                const float2 pa = *reinterpret_cast<const float2*>(Pr + c0);
                const float2 pbv = *reinterpret_cast<const float2*>(Pr + c0 + 8);
                float v0 = pa.x + sB1[c0];
                float v1 = pa.y + sB1[c0 + 1];
                float v2 = pbv.x + sB1[c0 + 8];
                float v3 = pbv.y + sB1[c0 + 9];
                #pragma unroll
                for (int j = 0; j < 8; j++) {
                    const float* wr = sW1L + j * 64 + c0;
                    v0 = fmaf(lab[j], wr[0], v0);
                    v1 = fmaf(lab[j], wr[1], v1);
                    v2 = fmaf(lab[j], wr[8], v2);
                    v3 = fmaf(lab[j], wr[9], v3);
                }
                ah[kt*4 + sl]     = pack_h2(fmaxf(v0, 0.f), fmaxf(v1, 0.f));
                ah[kt*4 + 2 + sl] = pack_h2(fmaxf(v2, 0.f), fmaxf(v3, 0.f));
            }
        }

        float D[64];

        // ================= LAYER 2: o = relu(h @ W2 + b2) =================
        gemm64x2_1t(D, ahA, ahB, sBF, lane);
        {
            u32 p01[8], p23[8], q01[8], q23[8];   // rows pb, pb+8, pb+16, pb+24
            #pragma unroll
            for (int nt = 0; nt < 8; nt++) {
                const int c0 = nt * 8 + q2;
                const int kt = nt >> 1, hf = nt & 1;
                const float b0 = sB2[c0], b1 = sB2[c0 + 1];
                p01[nt] = pack_h2(fmaxf(D[nt*8+0] + b0, 0.f), fmaxf(D[nt*8+1] + b1, 0.f));
                p23[nt] = pack_h2(fmaxf(D[nt*8+2] + b0, 0.f), fmaxf(D[nt*8+3] + b1, 0.f));
                q01[nt] = pack_h2(fmaxf(D[nt*8+4] + b0, 0.f), fmaxf(D[nt*8+5] + b1, 0.f));
                q23[nt] = pack_h2(fmaxf(D[nt*8+6] + b0, 0.f), fmaxf(D[nt*8+7] + b1, 0.f));
                ahA[kt*4 + hf*2 + 0] = p01[nt];
                ahA[kt*4 + hf*2 + 1] = p23[nt];
                ahB[kt*4 + hf*2 + 0] = q01[nt];
                ahB[kt*4 + hf*2 + 1] = q23[nt];
            }
            // coalesced stores: each quad writes a full 128B row segment
            const int slot = (lane & 3) * 8;
            uint4* r0 = reinterpret_cast<uint4*>(&g_O16[(size_t)(pb     ) * 32 + slot]);
            uint4* r1 = reinterpret_cast<uint4*>(&g_O16[(size_t)(pb +  8) * 32 + slot]);
            uint4* r2 = reinterpret_cast<uint4*>(&g_O16[(size_t)(pb + 16) * 32 + slot]);
            uint4* r3 = reinterpret_cast<uint4*>(&g_O16[(size_t)(pb + 24) * 32 + slot]);
            r0[0] = make_uint4(p01[0], p01[1], p01[2], p01[3]);
            r0[1] = make_uint4(p01[4], p01[5], p01[6], p01[7]);
            r1[0] = make_uint4(p23[0], p23[1], p23[2], p23[3]);
            r1[1] = make_uint4(p23[4], p23[5], p23[6], p23[7]);
            r2[0] = make_uint4(q01[0], q01[1], q01[2], q01[3]);
            r2[1] = make_uint4(q01[4], q01[5], q01[6], q01[7]);
            r3[0] = make_uint4(q23[0], q23[1], q23[2], q23[3]);
            r3[1] = make_uint4(q23[4], q23[5], q23[6], q23[7]);
        }

        // ===== LAYER 3: a = relu(o @ A1a + A1B[node] + b) (scores only) ===
        const float* G[4];
        #pragma unroll
        for (int rr = 0; rr < 4; rr++)
            G[rr] = g_A1B + (size_t)__ldg(&nodes[(pb + rr * 8) / K_N]) * 64;

        gemm64x2_1t(D, ahA, ahB, sBF + 2048, lane);
        #pragma unroll
        for (int nt = 0; nt < 8; nt++) {
            const int c0 = nt * 8 + q2;
            const int kt = nt >> 1, hf = nt & 1;
            #pragma unroll
            for (int half = 0; half < 2; half++) {
                const float2 g0 = *reinterpret_cast<const float2*>(G[half*2]     + c0);
                const float2 g1 = *reinterpret_cast<const float2*>(G[half*2 + 1] + c0);
                const float b0 = sBa1[c0], b1 = sBa1[c0 + 1];
                const float v0 = fmaxf(D[nt*8 + half*4 + 0] + b0 + g0.x, 0.f);
                const float v1 = fmaxf(D[nt*8 + half*4 + 1] + b1 + g0.y, 0.f);
                const float v2 = fmaxf(D[nt*8 + half*4 + 2] + b0 + g1.x, 0.f);
                const float v3 = fmaxf(D[nt*8 + half*4 + 3] + b1 + g1.y, 0.f);
                u32* ah = half ? ahB : ahA;
                ah[kt*4 + hf*2 + 0] = pack_h2(v0, v1);
                ah[kt*4 + hf*2 + 1] = pack_h2(v2, v3);
            }
        }

        // ========= LAYER 4: a2 = relu(a @ A2 + b); score = a2 . a3 ========
        gemm64x2_1t(D, ahA, ahB, sBF + 4096, lane);
        float s[4] = {0.f, 0.f, 0.f, 0.f};
        #pragma unroll
        for (int nt = 0; nt < 8; nt++) {
            const int c0 = nt * 8 + q2;
            const float b0 = sBa2[c0], b1 = sBa2[c0 + 1];
            const float w0 = sA3[c0],  w1 = sA3[c0 + 1];
            #pragma unroll
            for (int half = 0; half < 2; half++) {
                const float v0 = fmaxf(D[nt*8 + half*4 + 0] + b0, 0.f);
                const float v1 = fmaxf(D[nt*8 + half*4 + 1] + b1, 0.f);
                const float v2 = fmaxf(D[nt*8 + half*4 + 2] + b0, 0.f);
                const float v3 = fmaxf(D[nt*8 + half*4 + 3] + b1, 0.f);
                s[half*2]     = fmaf(v0, w0, fmaf(v1, w1, s[half*2]));
                s[half*2 + 1] = fmaf(v2, w0, fmaf(v3, w1, s[half*2 + 1]));
            }
        }
        #pragma unroll
        for (int rr = 0; rr < 4; rr++) {
            float sv = s[rr];
            sv += __shfl_xor_sync(0xffffffffu, sv, 1);
            sv += __shfl_xor_sync(0xffffffffu, sv, 2);
            if ((lane & 3) == 0) g_S[pb + rr * 8] = sv + a3b0;
        }
    }
}

// ---------------------------------------------------------------------------
// Kernel 3: masked softmax + aggregate. fp16 o reads; lane -> column map:
// slot=lane ↔ columns (lane&7)*8 + (lane>>3)*2 + {0,1}.
// ---------------------------------------------------------------------------
__global__ void __launch_bounds__(256) k_agg(const int*   __restrict__ nodes,
                                             const int*   __restrict__ nlen,
                                             const float* __restrict__ u2e,
                                             float*       __restrict__ out)
{
    const int wid  = (blockIdx.x * 256 + threadIdx.x) >> 5;
    const int lane = threadIdx.x & 31;
    if (wid >= B_N) return;
    const int b   = wid;
    const int len = nlen[b];

    if (len <= 0) {
        const int node = nodes[b];
        const float2* src = reinterpret_cast<const float2*>(u2e + (size_t)node * 64);
        reinterpret_cast<float2*>(out + (size_t)b * 64)[lane] = src[lane];
        return;
    }

    const float* Sb = g_S + (size_t)b * K_N;
    float s0 = (lane      < len) ? Sb[lane]      : -3.0e38f;
    float s1 = (lane + 32 < len) ? Sb[lane + 32] : -3.0e38f;

    float m = fmaxf(s0, s1);
    #pragma unroll
    for (int o = 16; o > 0; o >>= 1) m = fmaxf(m, __shfl_xor_sync(0xffffffffu, m, o));

    const float e0 = (lane      < len) ? expf(s0 - m) : 0.f;
    const float e1 = (lane + 32 < len) ? expf(s1 - m) : 0.f;

    float ss = e0 + e1;
    #pragma unroll
    for (int o = 16; o > 0; o >>= 1) ss += __shfl_xor_sync(0xffffffffu, ss, o);

    const float inv = 1.f / ss;
    const float w0 = e0 * inv;
    const float w1 = e1 * inv;

    float2 agg = make_float2(0.f, 0.f);
    const u32* Ob = g_O16 + (size_t)b * K_N * 32;
    for (int k = 0; k < len; k++) {
        const float ak = (k < 32) ? __shfl_sync(0xffffffffu, w0, k)
                                  : __shfl_sync(0xffffffffu, w1, k - 32);
        const u32 ov = Ob[k * 32 + lane];
        const float2 of = __half22float2(*reinterpret_cast<const __half2*>(&ov));
        agg.x = fmaf(ak, of.x, agg.x);
        agg.y = fmaf(ak, of.y, agg.y);
    }
    const int col = (lane & 7) * 8 + (lane >> 3) * 2;
    *reinterpret_cast<float2*>(out + (size_t)b * 64 + col) = agg;
}

// ---------------------------------------------------------------------------
// kernel_launch
// ---------------------------------------------------------------------------
extern "C" void kernel_launch(void* const* d_in, const int* in_sizes, int n_in,
                              void* d_out, int out_size)
{
    const int*   nodes  = (const int*)  d_in[0];
    const int*   nidx   = (const int*)  d_in[1];
    const int*   nlen   = (const int*)  d_in[2];
    const float* labels = (const float*)d_in[3];
    const float* u2e    = (const float*)d_in[4];
    const float* w1W    = (const float*)d_in[5];
    const float* w1b    = (const float*)d_in[6];
    const float* w2W    = (const float*)d_in[7];
    const float* w2b    = (const float*)d_in[8];
    const float* a1W    = (const float*)d_in[9];
    const float* a1b    = (const float*)d_in[10];
    const float* a2W    = (const float*)d_in[11];
    const float* a2b    = (const float*)d_in[12];
    const float* a3W    = (const float*)d_in[13];
    const float* a3b    = (const float*)d_in[14];
    float* out = (float*)d_out;

    cudaFuncSetAttribute(k_main, cudaFuncAttributeMaxDynamicSharedMemorySize, DSM_BYTES);

    k_wfrag<<<20, 256>>>(w2W, a1W, a2W, w1W);
    k_pre  <<<(VTILE + 7) / 8, 256>>>(u2e);
    k_main <<<296, 128, DSM_BYTES>>>(nodes, nidx, labels, w1W, w1b,
                                     w2b, a1b, a2b, a3W, a3b);
    k_agg  <<<(B_N * 32 + 255) / 256, 256>>>(nodes, nlen, u2e, out);
}

// round 13
// speedup vs baseline: 1.6287x; 1.1178x over previous
#include <cuda_runtime.h>
#include <cuda_fp16.h>
#include <cstdint>
#include <math.h>

#define B_N   16384
#define K_N   50
#define V_N   100000
#define BK_N  (B_N * K_N)          // 819200
#define NTILE (BK_N / 128)         // 6400 tiles of 128 pairs
#define VTILE (V_N / 16)           // 6250 vocab warp-tiles

typedef unsigned int u32;

// ---------------------------------------------------------------------------
// Device scratch (static — no cudaMalloc allowed)
// ---------------------------------------------------------------------------
__device__ float g_P  [(size_t)V_N * 64];      // u2e @ w1_W[0:64,:]
__device__ float g_A1B[(size_t)V_N * 64];      // u2e @ a1_W[64:128,:]
// o_history fp16x2: row = pair, 32 u32/row; slot (l4*8 + nt) = cols nt*8+l4*2+{0,1}
__device__ u32   g_O16[(size_t)BK_N * 32];     // 105MB
__device__ float g_S  [(size_t)BK_N];          // attention scores
// fp16 B fragments: blocks of 2048 u32, layout [kt:4][nt:8][lane:32][reg:2]
// L: 0=w2W  1=a1W[0:64]  2=a2W  3=w1W[0:64]  4=a1W[64:128]
// L=5: W1X = [w1W[64:72]; w1b; 0...] K=16 — only kt=0 (512 u32) used
__device__ u32   g_Wf [6 * 2048];              // 48KB

// ---------------------------------------------------------------------------
// fp16 helpers
// ---------------------------------------------------------------------------
__device__ __forceinline__ u32 pack_h2(float v0, float v1) {
    __half2 h = __floats2half2_rn(v0, v1);
    return *reinterpret_cast<u32*>(&h);
}
__device__ __forceinline__ void split2h(float v0, float v1, u32& h, u32& l) {
    const __half2 hh = __floats2half2_rn(v0, v1);
    h = *reinterpret_cast<const u32*>(&hh);
    const float2 hf = __half22float2(hh);
    const __half2 ll = __floats2half2_rn(v0 - hf.x, v1 - hf.y);
    l = *reinterpret_cast<const u32*>(&ll);
}
// m16n8k16 row.col fp16 MMA, fp32 accumulate (sm_80+ baseline)
__device__ __forceinline__ void mma16816(float& d0, float& d1, float& d2, float& d3,
                                         u32 a0, u32 a1, u32 a2, u32 a3,
                                         u32 b0, u32 b1) {
    asm("mma.sync.aligned.m16n8k16.row.col.f32.f16.f16.f32 "
        "{%0,%1,%2,%3}, {%4,%5,%6,%7}, {%8,%9}, {%0,%1,%2,%3};"
        : "+f"(d0), "+f"(d1), "+f"(d2), "+f"(d3)
        : "r"(a0), "r"(a1), "r"(a2), "r"(a3), "r"(b0), "r"(b1));
}

// ---------------------------------------------------------------------------
// Kernel 0: fp16 B-fragments. 5 full matrices + W1X (labels+bias, kt0 only).
// ---------------------------------------------------------------------------
__global__ void __launch_bounds__(256) k_wfrag(const float* __restrict__ w2W,
                                               const float* __restrict__ a1W,
                                               const float* __restrict__ a2W,
                                               const float* __restrict__ w1W,
                                               const float* __restrict__ w1b)
{
    const int idx = blockIdx.x * 256 + threadIdx.x;   // 5120 + 256 = 5376
    if (idx >= 5376) return;

    if (idx >= 5120) {
        // L=5: W1X[k][n]: k<8 -> w1W[(64+k)*64+n], k==8 -> w1b[n], else 0
        const int e    = idx - 5120;      // 0..255
        const int lane = e & 31;
        const int nt   = e >> 5;          // 0..7
        const int n  = nt * 8 + (lane >> 2);
        const int k0 = (lane & 3) * 2;    // 0,2,4,6
        const float w00 = w1W[(64 + k0    ) * 64 + n];
        const float w01 = w1W[(64 + k0 + 1) * 64 + n];
        const float w10 = (k0 == 0) ? w1b[n] : 0.f;   // row k0+8: 8->bias, else 0
        const float w11 = 0.f;
        const int f = 5 * 2048 + (nt * 32 + lane) * 2;
        g_Wf[f]     = pack_h2(w00, w01);
        g_Wf[f + 1] = pack_h2(w10, w11);
        return;
    }

    const int lane = idx & 31;
    const int nt   = (idx >> 5) & 7;
    const int kt   = (idx >> 8) & 3;
    const int L    = idx >> 10;

    const float* W;
    if (L == 0)      W = w2W;
    else if (L == 1) W = a1W;
    else if (L == 2) W = a2W;
    else if (L == 3) W = w1W;
    else             W = a1W + 4096;    // rows 64..127

    const int n  = nt * 8 + (lane >> 2);
    const int k0 = kt * 16 + (lane & 3) * 2;

    const int f = L * 2048 + ((kt*8 + nt)*32 + lane)*2;
    g_Wf[f]     = pack_h2(W[k0*64+n],     W[(k0+1)*64+n]);
    g_Wf[f + 1] = pack_h2(W[(k0+8)*64+n], W[(k0+9)*64+n]);
}

// ---------------------------------------------------------------------------
// Single-tile 64->64 GEMM (M=16): 2-term fp16 split — k_pre only.
// ---------------------------------------------------------------------------
__device__ __forceinline__ void gemm64(float* D, const u32* ah, const u32* al,
                                       const u32* sBFL, int lane)
{
    #pragma unroll
    for (int nt = 0; nt < 8; nt++) {
        float d0=0.f,d1=0.f,d2=0.f,d3=0.f;
        #pragma unroll
        for (int kt = 0; kt < 4; kt++) {
            const uint2 b = *reinterpret_cast<const uint2*>(sBFL + (kt*8 + nt)*64 + lane*2);
            mma16816(d0,d1,d2,d3, ah[kt*4],ah[kt*4+1],ah[kt*4+2],ah[kt*4+3], b.x,b.y);
            mma16816(d0,d1,d2,d3, al[kt*4],al[kt*4+1],al[kt*4+2],al[kt*4+3], b.x,b.y);
        }
        D[nt*4+0]=d0; D[nt*4+1]=d1; D[nt*4+2]=d2; D[nt*4+3]=d3;
    }
}

// Dual-tile (M=32), single-term A: k_main layers 2-4.
__device__ __forceinline__ void gemm64x2_1t(float* D,
                                            const u32* ahA, const u32* ahB,
                                            const u32* sBFL, int lane)
{
    #pragma unroll
    for (int nt = 0; nt < 8; nt++) {
        float d0=0.f,d1=0.f,d2=0.f,d3=0.f,d4=0.f,d5=0.f,d6=0.f,d7=0.f;
        #pragma unroll
        for (int kt = 0; kt < 4; kt++) {
            const uint2 b = *reinterpret_cast<const uint2*>(sBFL + (kt*8 + nt)*64 + lane*2);
            mma16816(d0,d1,d2,d3, ahA[kt*4],ahA[kt*4+1],ahA[kt*4+2],ahA[kt*4+3], b.x,b.y);
            mma16816(d4,d5,d6,d7, ahB[kt*4],ahB[kt*4+1],ahB[kt*4+2],ahB[kt*4+3], b.x,b.y);
        }
        D[nt*8+0]=d0; D[nt*8+1]=d1; D[nt*8+2]=d2; D[nt*8+3]=d3;
        D[nt*8+4]=d4; D[nt*8+5]=d5; D[nt*8+6]=d6; D[nt*8+7]=d7;
    }
}

// ---------------------------------------------------------------------------
// Kernel 1: HMMA per-vocab precompute of P and A1B (2-term, accurate tables).
// ---------------------------------------------------------------------------
__global__ void __launch_bounds__(256) k_pre(const float* __restrict__ u2e)
{
    __shared__ u32 sBF[4096];

    const int tid = threadIdx.x;
    {
        const uint4* src = reinterpret_cast<const uint4*>(g_Wf + 3 * 2048);
        uint4* dst = reinterpret_cast<uint4*>(sBF);
        for (int i = tid; i < 1024; i += 256) dst[i] = src[i];
    }
    __syncthreads();

    const int wid  = tid >> 5;
    const int lane = tid & 31;
    const int g    = lane >> 2;
    const int q2   = (lane & 3) << 1;

    const int wt = blockIdx.x * 8 + wid;
    if (wt >= VTILE) return;
    const int v0 = wt * 16 + g;
    const int v1 = v0 + 8;

    u32 ah[16], al[16];
    #pragma unroll
    for (int rr = 0; rr < 2; rr++) {
        const float* Mr = u2e + (size_t)(wt*16 + g + rr*8) * 64;
        #pragma unroll
        for (int kt = 0; kt < 4; kt++) {
            const int c0 = kt*16 + q2;
            const float2 pa = *reinterpret_cast<const float2*>(Mr + c0);
            const float2 pb = *reinterpret_cast<const float2*>(Mr + c0 + 8);
            split2h(pa.x, pa.y, ah[kt*4 + rr],     al[kt*4 + rr]);
            split2h(pb.x, pb.y, ah[kt*4 + 2 + rr], al[kt*4 + 2 + rr]);
        }
    }

    float D[32];
    gemm64(D, ah, al, sBF, lane);
    #pragma unroll
    for (int nt = 0; nt < 8; nt++) {
        const int c0 = nt*8 + q2;
        *reinterpret_cast<float2*>(g_P + (size_t)v0*64 + c0) = make_float2(D[nt*4+0], D[nt*4+1]);
        *reinterpret_cast<float2*>(g_P + (size_t)v1*64 + c0) = make_float2(D[nt*4+2], D[nt*4+3]);
    }
    gemm64(D, ah, al, sBF + 2048, lane);
    #pragma unroll
    for (int nt = 0; nt < 8; nt++) {
        const int c0 = nt*8 + q2;
        *reinterpret_cast<float2*>(g_A1B + (size_t)v0*64 + c0) = make_float2(D[nt*4+0], D[nt*4+1]);
        *reinterpret_cast<float2*>(g_A1B + (size_t)v1*64 + c0) = make_float2(D[nt*4+2], D[nt*4+3]);
    }
}

// ---------------------------------------------------------------------------
// Main kernel: layer 1 via MMA (labels+bias folded), layers 2-4 via MMA.
// Each warp: 32 pairs. Coalesced 128B-row fp16 o stores.
// ---------------------------------------------------------------------------
#define DSM_U32  (6144 + 512 + 4*64)   // 6912 u32 = 27648 B
#define DSM_BYTES (DSM_U32 * 4)

__global__ void __launch_bounds__(128, 2) k_main(
    const int*   __restrict__ nodes,
    const int*   __restrict__ nidx,
    const float* __restrict__ labels,
    const float* __restrict__ w2b,
    const float* __restrict__ a1b,
    const float* __restrict__ a2b,
    const float* __restrict__ a3W,
    const float* __restrict__ a3b)
{
    extern __shared__ u32 dsm[];
    u32*   sBF  = dsm;                       // 6144 u32: L=0,1,2
    u32*   sBF1 = dsm + 6144;                // 512 u32: W1X kt0
    float* sB2  = (float*)(dsm + 6656);      // 64
    float* sBa1 = sB2 + 64;
    float* sBa2 = sBa1 + 64;
    float* sA3  = sBa2 + 64;

    const int tid = threadIdx.x;
    {
        const uint4* src = reinterpret_cast<const uint4*>(g_Wf);
        uint4* dst = reinterpret_cast<uint4*>(sBF);
        for (int i = tid; i < 1536; i += 128) dst[i] = src[i];
        const uint4* src1 = reinterpret_cast<const uint4*>(g_Wf + 5 * 2048);
        uint4* dst1 = reinterpret_cast<uint4*>(sBF1);
        if (tid < 128) dst1[tid] = src1[tid];
        if (tid < 64) {
            sB2 [tid] = w2b[tid];
            sBa1[tid] = a1b[tid];
            sBa2[tid] = a2b[tid];
            sA3 [tid] = a3W[tid];
        }
    }
    __syncthreads();

    const float a3b0 = a3b[0];
    const int wid  = tid >> 5;             // 0..3
    const int lane = tid & 31;
    const int g    = lane >> 2;            // 0..7
    const int q2   = (lane & 3) << 1;      // 0,2,4,6
    const u32 onehot = (q2 == 0) ? pack_h2(1.f, 0.f) : 0u;

    for (int t = blockIdx.x; t < NTILE; t += gridDim.x) {
        const int pb = t * 128 + wid * 32 + g;   // rows pb, pb+8, pb+16, pb+24

        u32 ahA[16], ahB[16];
        float D[64];

        // ====== LAYER 1 via MMA: D = [labels,1,0..] @ [W1L; b1; 0] ======
        {
            u32 lF[8];
            const float* Pr[4];
            #pragma unroll
            for (int rr = 0; rr < 4; rr++) {
                const int p = pb + rr * 8;
                const float2 l2 = *reinterpret_cast<const float2*>(labels + (size_t)p * 8 + q2);
                u32* lf = (rr < 2) ? lF : lF + 4;
                const int sl = rr & 1;
                lf[0 + sl] = pack_h2(l2.x, l2.y);
                lf[2 + sl] = onehot;
                Pr[rr] = g_P + (size_t)__ldg(&nidx[p]) * 64;
            }

            #pragma unroll
            for (int nt = 0; nt < 8; nt++) {
                float d0=0.f,d1=0.f,d2=0.f,d3=0.f,d4=0.f,d5=0.f,d6=0.f,d7=0.f;
                const uint2 b = *reinterpret_cast<const uint2*>(sBF1 + nt*64 + lane*2);
                mma16816(d0,d1,d2,d3, lF[0],lF[1],lF[2],lF[3], b.x,b.y);
                mma16816(d4,d5,d6,d7, lF[4],lF[5],lF[6],lF[7], b.x,b.y);
                D[nt*8+0]=d0; D[nt*8+1]=d1; D[nt*8+2]=d2; D[nt*8+3]=d3;
                D[nt*8+4]=d4; D[nt*8+5]=d5; D[nt*8+6]=d6; D[nt*8+7]=d7;
            }

            // h = relu(D + P[ni]) -> A fragments (hi only)
            #pragma unroll
            for (int nt = 0; nt < 8; nt++) {
                const int c0 = nt * 8 + q2;
                const int kt = nt >> 1, hf = nt & 1;
                #pragma unroll
                for (int half = 0; half < 2; half++) {
                    const float2 g0 = *reinterpret_cast<const float2*>(Pr[half*2]     + c0);
                    const float2 g1 = *reinterpret_cast<const float2*>(Pr[half*2 + 1] + c0);
                    const float v0 = fmaxf(D[nt*8 + half*4 + 0] + g0.x, 0.f);
                    const float v1 = fmaxf(D[nt*8 + half*4 + 1] + g0.y, 0.f);
                    const float v2 = fmaxf(D[nt*8 + half*4 + 2] + g1.x, 0.f);
                    const float v3 = fmaxf(D[nt*8 + half*4 + 3] + g1.y, 0.f);
                    u32* ah = half ? ahB : ahA;
                    ah[kt*4 + hf*2 + 0] = pack_h2(v0, v1);
                    ah[kt*4 + hf*2 + 1] = pack_h2(v2, v3);
                }
            }
        }

        // ================= LAYER 2: o = relu(h @ W2 + b2) =================
        gemm64x2_1t(D, ahA, ahB, sBF, lane);
        {
            u32 p01[8], p23[8], q01[8], q23[8];
            #pragma unroll
            for (int nt = 0; nt < 8; nt++) {
                const int c0 = nt * 8 + q2;
                const int kt = nt >> 1, hf = nt & 1;
                const float b0 = sB2[c0], b1 = sB2[c0 + 1];
                p01[nt] = pack_h2(fmaxf(D[nt*8+0] + b0, 0.f), fmaxf(D[nt*8+1] + b1, 0.f));
                p23[nt] = pack_h2(fmaxf(D[nt*8+2] + b0, 0.f), fmaxf(D[nt*8+3] + b1, 0.f));
                q01[nt] = pack_h2(fmaxf(D[nt*8+4] + b0, 0.f), fmaxf(D[nt*8+5] + b1, 0.f));
                q23[nt] = pack_h2(fmaxf(D[nt*8+6] + b0, 0.f), fmaxf(D[nt*8+7] + b1, 0.f));
                ahA[kt*4 + hf*2 + 0] = p01[nt];
                ahA[kt*4 + hf*2 + 1] = p23[nt];
                ahB[kt*4 + hf*2 + 0] = q01[nt];
                ahB[kt*4 + hf*2 + 1] = q23[nt];
            }
            const int slot = (lane & 3) * 8;
            uint4* r0 = reinterpret_cast<uint4*>(&g_O16[(size_t)(pb     ) * 32 + slot]);
            uint4* r1 = reinterpret_cast<uint4*>(&g_O16[(size_t)(pb +  8) * 32 + slot]);
            uint4* r2 = reinterpret_cast<uint4*>(&g_O16[(size_t)(pb + 16) * 32 + slot]);
            uint4* r3 = reinterpret_cast<uint4*>(&g_O16[(size_t)(pb + 24) * 32 + slot]);
            r0[0] = make_uint4(p01[0], p01[1], p01[2], p01[3]);
            r0[1] = make_uint4(p01[4], p01[5], p01[6], p01[7]);
            r1[0] = make_uint4(p23[0], p23[1], p23[2], p23[3]);
            r1[1] = make_uint4(p23[4], p23[5], p23[6], p23[7]);
            r2[0] = make_uint4(q01[0], q01[1], q01[2], q01[3]);
            r2[1] = make_uint4(q01[4], q01[5], q01[6], q01[7]);
            r3[0] = make_uint4(q23[0], q23[1], q23[2], q23[3]);
            r3[1] = make_uint4(q23[4], q23[5], q23[6], q23[7]);
        }

        // ===== LAYER 3: a = relu(o @ A1a + A1B[node] + b) (scores only) ===
        const float* G[4];
        #pragma unroll
        for (int rr = 0; rr < 4; rr++)
            G[rr] = g_A1B + (size_t)__ldg(&nodes[(pb + rr * 8) / K_N]) * 64;

        gemm64x2_1t(D, ahA, ahB, sBF + 2048, lane);
        #pragma unroll
        for (int nt = 0; nt < 8; nt++) {
            const int c0 = nt * 8 + q2;
            const int kt = nt >> 1, hf = nt & 1;
            #pragma unroll
            for (int half = 0; half < 2; half++) {
                const float2 g0 = *reinterpret_cast<const float2*>(G[half*2]     + c0);
                const float2 g1 = *reinterpret_cast<const float2*>(G[half*2 + 1] + c0);
                const float b0 = sBa1[c0], b1 = sBa1[c0 + 1];
                const float v0 = fmaxf(D[nt*8 + half*4 + 0] + b0 + g0.x, 0.f);
                const float v1 = fmaxf(D[nt*8 + half*4 + 1] + b1 + g0.y, 0.f);
                const float v2 = fmaxf(D[nt*8 + half*4 + 2] + b0 + g1.x, 0.f);
                const float v3 = fmaxf(D[nt*8 + half*4 + 3] + b1 + g1.y, 0.f);
                u32* ah = half ? ahB : ahA;
                ah[kt*4 + hf*2 + 0] = pack_h2(v0, v1);
                ah[kt*4 + hf*2 + 1] = pack_h2(v2, v3);
            }
        }

        // ========= LAYER 4: a2 = relu(a @ A2 + b); score = a2 . a3 ========
        gemm64x2_1t(D, ahA, ahB, sBF + 4096, lane);
        float s[4] = {0.f, 0.f, 0.f, 0.f};
        #pragma unroll
        for (int nt = 0; nt < 8; nt++) {
            const int c0 = nt * 8 + q2;
            const float b0 = sBa2[c0], b1 = sBa2[c0 + 1];
            const float w0 = sA3[c0],  w1 = sA3[c0 + 1];
            #pragma unroll
            for (int half = 0; half < 2; half++) {
                const float v0 = fmaxf(D[nt*8 + half*4 + 0] + b0, 0.f);
                const float v1 = fmaxf(D[nt*8 + half*4 + 1] + b1, 0.f);
                const float v2 = fmaxf(D[nt*8 + half*4 + 2] + b0, 0.f);
                const float v3 = fmaxf(D[nt*8 + half*4 + 3] + b1, 0.f);
                s[half*2]     = fmaf(v0, w0, fmaf(v1, w1, s[half*2]));
                s[half*2 + 1] = fmaf(v2, w0, fmaf(v3, w1, s[half*2 + 1]));
            }
        }
        #pragma unroll
        for (int rr = 0; rr < 4; rr++) {
            float sv = s[rr];
            sv += __shfl_xor_sync(0xffffffffu, sv, 1);
            sv += __shfl_xor_sync(0xffffffffu, sv, 2);
            if ((lane & 3) == 0) g_S[pb + rr * 8] = sv + a3b0;
        }
    }
}

// ---------------------------------------------------------------------------
// Kernel 3: masked softmax + aggregate (R12 proven). Column map:
// slot=lane ↔ columns (lane&7)*8 + (lane>>3)*2 + {0,1}.
// ---------------------------------------------------------------------------
__global__ void __launch_bounds__(256) k_agg(const int*   __restrict__ nodes,
                                             const int*   __restrict__ nlen,
                                             const float* __restrict__ u2e,
                                             float*       __restrict__ out)
{
    const int wid  = (blockIdx.x * 256 + threadIdx.x) >> 5;
    const int lane = threadIdx.x & 31;
    if (wid >= B_N) return;
    const int b   = wid;
    const int len = nlen[b];

    if (len <= 0) {
        const int node = nodes[b];
        const float2* src = reinterpret_cast<const float2*>(u2e + (size_t)node * 64);
        reinterpret_cast<float2*>(out + (size_t)b * 64)[lane] = src[lane];
        return;
    }

    const float* Sb = g_S + (size_t)b * K_N;
    float s0 = (lane      < len) ? Sb[lane]      : -3.0e38f;
    float s1 = (lane + 32 < len) ? Sb[lane + 32] : -3.0e38f;

    float m = fmaxf(s0, s1);
    #pragma unroll
    for (int o = 16; o > 0; o >>= 1) m = fmaxf(m, __shfl_xor_sync(0xffffffffu, m, o));

    const float e0 = (lane      < len) ? expf(s0 - m) : 0.f;
    const float e1 = (lane + 32 < len) ? expf(s1 - m) : 0.f;

    float ss = e0 + e1;
    #pragma unroll
    for (int o = 16; o > 0; o >>= 1) ss += __shfl_xor_sync(0xffffffffu, ss, o);

    const float inv = 1.f / ss;
    const float w0 = e0 * inv;
    const float w1 = e1 * inv;

    float2 agg = make_float2(0.f, 0.f);
    const u32* Ob = g_O16 + (size_t)b * K_N * 32;
    for (int k = 0; k < len; k++) {
        const float ak = (k < 32) ? __shfl_sync(0xffffffffu, w0, k)
                                  : __shfl_sync(0xffffffffu, w1, k - 32);
        const u32 ov = Ob[k * 32 + lane];
        const float2 of = __half22float2(*reinterpret_cast<const __half2*>(&ov));
        agg.x = fmaf(ak, of.x, agg.x);
        agg.y = fmaf(ak, of.y, agg.y);
    }
    const int col = (lane & 7) * 8 + (lane >> 3) * 2;
    *reinterpret_cast<float2*>(out + (size_t)b * 64 + col) = agg;
}

// ---------------------------------------------------------------------------
// kernel_launch
// ---------------------------------------------------------------------------
extern "C" void kernel_launch(void* const* d_in, const int* in_sizes, int n_in,
                              void* d_out, int out_size)
{
    const int*   nodes  = (const int*)  d_in[0];
    const int*   nidx   = (const int*)  d_in[1];
    const int*   nlen   = (const int*)  d_in[2];
    const float* labels = (const float*)d_in[3];
    const float* u2e    = (const float*)d_in[4];
    const float* w1W    = (const float*)d_in[5];
    const float* w1b    = (const float*)d_in[6];
    const float* w2W    = (const float*)d_in[7];
    const float* w2b    = (const float*)d_in[8];
    const float* a1W    = (const float*)d_in[9];
    const float* a1b    = (const float*)d_in[10];
    const float* a2W    = (const float*)d_in[11];
    const float* a2b    = (const float*)d_in[12];
    const float* a3W    = (const float*)d_in[13];
    const float* a3b    = (const float*)d_in[14];
    float* out = (float*)d_out;

    cudaFuncSetAttribute(k_main, cudaFuncAttributeMaxDynamicSharedMemorySize, DSM_BYTES);

    k_wfrag<<<21, 256>>>(w2W, a1W, a2W, w1W, w1b);
    k_pre  <<<(VTILE + 7) / 8, 256>>>(u2e);
    k_main <<<296, 128, DSM_BYTES>>>(nodes, nidx, labels,
                                     w2b, a1b, a2b, a3W, a3b);
    k_agg  <<<(B_N * 32 + 255) / 256, 256>>>(nodes, nlen, u2e, out);
}

// round 14
// speedup vs baseline: 1.7904x; 1.0993x over previous
#include <cuda_runtime.h>
#include <cuda_fp16.h>
#include <cstdint>
#include <math.h>

#define B_N   16384
#define K_N   50
#define V_N   100000
#define BK_N  (B_N * K_N)          // 819200
#define NTILE (BK_N / 128)         // 6400 tiles of 128 pairs
#define VTILE (V_N / 16)           // 6250 vocab warp-tiles

typedef unsigned int u32;

// ---------------------------------------------------------------------------
// Device scratch (static — no cudaMalloc allowed)
// Slot layout (per 64-col row, 32 u32): slot s = l4*8 + nt holds columns
// nt*8 + l4*2 + {0,1} as fp16x2  (l4 = lane&3 of the owning quad).
// ---------------------------------------------------------------------------
__device__ u32   g_P16  [(size_t)V_N * 32];    // 12.8MB fp16 table
__device__ u32   g_A1B16[(size_t)V_N * 32];    // 12.8MB fp16 table
__device__ u32   g_O16  [(size_t)BK_N * 32];   // 105MB o_history
__device__ float g_S    [(size_t)BK_N];        // attention scores
// fp16 B fragments: blocks of 2048 u32, layout [kt:4][nt:8][lane:32][reg:2]
// L: 0=w2W  1=a1W[0:64]  2=a2W  3=w1W[0:64]  4=a1W[64:128]
// L=5: W1X = [w1W[64:72]; w1b; 0...] K=16 — only kt=0 (512 u32) used
__device__ u32   g_Wf [6 * 2048];              // 48KB

// ---------------------------------------------------------------------------
// fp16 helpers
// ---------------------------------------------------------------------------
__device__ __forceinline__ u32 pack_h2(float v0, float v1) {
    __half2 h = __floats2half2_rn(v0, v1);
    return *reinterpret_cast<u32*>(&h);
}
__device__ __forceinline__ float2 h2f(u32 v) {
    return __half22float2(*reinterpret_cast<const __half2*>(&v));
}
__device__ __forceinline__ void split2h(float v0, float v1, u32& h, u32& l) {
    const __half2 hh = __floats2half2_rn(v0, v1);
    h = *reinterpret_cast<const u32*>(&hh);
    const float2 hf = __half22float2(hh);
    const __half2 ll = __floats2half2_rn(v0 - hf.x, v1 - hf.y);
    l = *reinterpret_cast<const u32*>(&ll);
}
// m16n8k16 row.col fp16 MMA, fp32 accumulate (sm_80+ baseline)
__device__ __forceinline__ void mma16816(float& d0, float& d1, float& d2, float& d3,
                                         u32 a0, u32 a1, u32 a2, u32 a3,
                                         u32 b0, u32 b1) {
    asm("mma.sync.aligned.m16n8k16.row.col.f32.f16.f16.f32 "
        "{%0,%1,%2,%3}, {%4,%5,%6,%7}, {%8,%9}, {%0,%1,%2,%3};"
        : "+f"(d0), "+f"(d1), "+f"(d2), "+f"(d3)
        : "r"(a0), "r"(a1), "r"(a2), "r"(a3), "r"(b0), "r"(b1));
}

// ---------------------------------------------------------------------------
// Kernel 0: fp16 B-fragments. 5 full matrices + W1X (labels+bias, kt0 only).
// ---------------------------------------------------------------------------
__global__ void __launch_bounds__(256) k_wfrag(const float* __restrict__ w2W,
                                               const float* __restrict__ a1W,
                                               const float* __restrict__ a2W,
                                               const float* __restrict__ w1W,
                                               const float* __restrict__ w1b)
{
    const int idx = blockIdx.x * 256 + threadIdx.x;   // 5120 + 256 = 5376
    if (idx >= 5376) return;

    if (idx >= 5120) {
        const int e    = idx - 5120;      // 0..255
        const int lane = e & 31;
        const int nt   = e >> 5;          // 0..7
        const int n  = nt * 8 + (lane >> 2);
        const int k0 = (lane & 3) * 2;    // 0,2,4,6
        const float w00 = w1W[(64 + k0    ) * 64 + n];
        const float w01 = w1W[(64 + k0 + 1) * 64 + n];
        const float w10 = (k0 == 0) ? w1b[n] : 0.f;
        const int f = 5 * 2048 + (nt * 32 + lane) * 2;
        g_Wf[f]     = pack_h2(w00, w01);
        g_Wf[f + 1] = pack_h2(w10, 0.f);
        return;
    }

    const int lane = idx & 31;
    const int nt   = (idx >> 5) & 7;
    const int kt   = (idx >> 8) & 3;
    const int L    = idx >> 10;

    const float* W;
    if (L == 0)      W = w2W;
    else if (L == 1) W = a1W;
    else if (L == 2) W = a2W;
    else if (L == 3) W = w1W;
    else             W = a1W + 4096;    // rows 64..127

    const int n  = nt * 8 + (lane >> 2);
    const int k0 = kt * 16 + (lane & 3) * 2;

    const int f = L * 2048 + ((kt*8 + nt)*32 + lane)*2;
    g_Wf[f]     = pack_h2(W[k0*64+n],     W[(k0+1)*64+n]);
    g_Wf[f + 1] = pack_h2(W[(k0+8)*64+n], W[(k0+9)*64+n]);
}

// ---------------------------------------------------------------------------
// Single-tile 64->64 GEMM (M=16): 2-term fp16 split — k_pre only.
// ---------------------------------------------------------------------------
__device__ __forceinline__ void gemm64(float* D, const u32* ah, const u32* al,
                                       const u32* sBFL, int lane)
{
    #pragma unroll
    for (int nt = 0; nt < 8; nt++) {
        float d0=0.f,d1=0.f,d2=0.f,d3=0.f;
        #pragma unroll
        for (int kt = 0; kt < 4; kt++) {
            const uint2 b = *reinterpret_cast<const uint2*>(sBFL + (kt*8 + nt)*64 + lane*2);
            mma16816(d0,d1,d2,d3, ah[kt*4],ah[kt*4+1],ah[kt*4+2],ah[kt*4+3], b.x,b.y);
            mma16816(d0,d1,d2,d3, al[kt*4],al[kt*4+1],al[kt*4+2],al[kt*4+3], b.x,b.y);
        }
        D[nt*4+0]=d0; D[nt*4+1]=d1; D[nt*4+2]=d2; D[nt*4+3]=d3;
    }
}

// Dual-tile (M=32), single-term A: k_main layers 2-4.
__device__ __forceinline__ void gemm64x2_1t(float* D,
                                            const u32* ahA, const u32* ahB,
                                            const u32* sBFL, int lane)
{
    #pragma unroll
    for (int nt = 0; nt < 8; nt++) {
        float d0=0.f,d1=0.f,d2=0.f,d3=0.f,d4=0.f,d5=0.f,d6=0.f,d7=0.f;
        #pragma unroll
        for (int kt = 0; kt < 4; kt++) {
            const uint2 b = *reinterpret_cast<const uint2*>(sBFL + (kt*8 + nt)*64 + lane*2);
            mma16816(d0,d1,d2,d3, ahA[kt*4],ahA[kt*4+1],ahA[kt*4+2],ahA[kt*4+3], b.x,b.y);
            mma16816(d4,d5,d6,d7, ahB[kt*4],ahB[kt*4+1],ahB[kt*4+2],ahB[kt*4+3], b.x,b.y);
        }
        D[nt*8+0]=d0; D[nt*8+1]=d1; D[nt*8+2]=d2; D[nt*8+3]=d3;
        D[nt*8+4]=d4; D[nt*8+5]=d5; D[nt*8+6]=d6; D[nt*8+7]=d7;
    }
}

// ---------------------------------------------------------------------------
// Kernel 1: HMMA per-vocab precompute of P16 and A1B16 (fp16 slot layout).
// ---------------------------------------------------------------------------
__global__ void __launch_bounds__(256) k_pre(const float* __restrict__ u2e)
{
    __shared__ u32 sBF[4096];

    const int tid = threadIdx.x;
    {
        const uint4* src = reinterpret_cast<const uint4*>(g_Wf + 3 * 2048);
        uint4* dst = reinterpret_cast<uint4*>(sBF);
        for (int i = tid; i < 1024; i += 256) dst[i] = src[i];
    }
    __syncthreads();

    const int wid  = tid >> 5;
    const int lane = tid & 31;
    const int g    = lane >> 2;
    const int q2   = (lane & 3) << 1;
    const int slot = (lane & 3) * 8;

    const int wt = blockIdx.x * 8 + wid;
    if (wt >= VTILE) return;
    const int v0 = wt * 16 + g;
    const int v1 = v0 + 8;

    u32 ah[16], al[16];
    #pragma unroll
    for (int rr = 0; rr < 2; rr++) {
        const float* Mr = u2e + (size_t)(wt*16 + g + rr*8) * 64;
        #pragma unroll
        for (int kt = 0; kt < 4; kt++) {
            const int c0 = kt*16 + q2;
            const float2 pa = *reinterpret_cast<const float2*>(Mr + c0);
            const float2 pb = *reinterpret_cast<const float2*>(Mr + c0 + 8);
            split2h(pa.x, pa.y, ah[kt*4 + rr],     al[kt*4 + rr]);
            split2h(pb.x, pb.y, ah[kt*4 + 2 + rr], al[kt*4 + 2 + rr]);
        }
    }

    float D[32];
    u32 p01[8], p23[8];

    gemm64(D, ah, al, sBF, lane);
    #pragma unroll
    for (int nt = 0; nt < 8; nt++) {
        p01[nt] = pack_h2(D[nt*4+0], D[nt*4+1]);
        p23[nt] = pack_h2(D[nt*4+2], D[nt*4+3]);
    }
    {
        uint4* r0 = reinterpret_cast<uint4*>(&g_P16[(size_t)v0 * 32 + slot]);
        uint4* r1 = reinterpret_cast<uint4*>(&g_P16[(size_t)v1 * 32 + slot]);
        r0[0] = make_uint4(p01[0], p01[1], p01[2], p01[3]);
        r0[1] = make_uint4(p01[4], p01[5], p01[6], p01[7]);
        r1[0] = make_uint4(p23[0], p23[1], p23[2], p23[3]);
        r1[1] = make_uint4(p23[4], p23[5], p23[6], p23[7]);
    }

    gemm64(D, ah, al, sBF + 2048, lane);
    #pragma unroll
    for (int nt = 0; nt < 8; nt++) {
        p01[nt] = pack_h2(D[nt*4+0], D[nt*4+1]);
        p23[nt] = pack_h2(D[nt*4+2], D[nt*4+3]);
    }
    {
        uint4* r0 = reinterpret_cast<uint4*>(&g_A1B16[(size_t)v0 * 32 + slot]);
        uint4* r1 = reinterpret_cast<uint4*>(&g_A1B16[(size_t)v1 * 32 + slot]);
        r0[0] = make_uint4(p01[0], p01[1], p01[2], p01[3]);
        r0[1] = make_uint4(p01[4], p01[5], p01[6], p01[7]);
        r1[0] = make_uint4(p23[0], p23[1], p23[2], p23[3]);
        r1[1] = make_uint4(p23[4], p23[5], p23[6], p23[7]);
    }
}

// ---------------------------------------------------------------------------
// Main kernel: layer 1 via MMA (labels+bias folded), layers 2-4 via MMA.
// fp16 slot-layout gathers for P and A1B.
// ---------------------------------------------------------------------------
#define DSM_U32  (6144 + 512 + 4*64)   // 6912 u32 = 27648 B
#define DSM_BYTES (DSM_U32 * 4)

__global__ void __launch_bounds__(128, 2) k_main(
    const int*   __restrict__ nodes,
    const int*   __restrict__ nidx,
    const float* __restrict__ labels,
    const float* __restrict__ w2b,
    const float* __restrict__ a1b,
    const float* __restrict__ a2b,
    const float* __restrict__ a3W,
    const float* __restrict__ a3b)
{
    extern __shared__ u32 dsm[];
    u32*   sBF  = dsm;                       // 6144 u32: L=0,1,2
    u32*   sBF1 = dsm + 6144;                // 512 u32: W1X kt0
    float* sB2  = (float*)(dsm + 6656);      // 64
    float* sBa1 = sB2 + 64;
    float* sBa2 = sBa1 + 64;
    float* sA3  = sBa2 + 64;

    const int tid = threadIdx.x;
    {
        const uint4* src = reinterpret_cast<const uint4*>(g_Wf);
        uint4* dst = reinterpret_cast<uint4*>(sBF);
        for (int i = tid; i < 1536; i += 128) dst[i] = src[i];
        const uint4* src1 = reinterpret_cast<const uint4*>(g_Wf + 5 * 2048);
        uint4* dst1 = reinterpret_cast<uint4*>(sBF1);
        if (tid < 128) dst1[tid] = src1[tid];
        if (tid < 64) {
            sB2 [tid] = w2b[tid];
            sBa1[tid] = a1b[tid];
            sBa2[tid] = a2b[tid];
            sA3 [tid] = a3W[tid];
        }
    }
    __syncthreads();

    const float a3b0 = a3b[0];
    const int wid  = tid >> 5;             // 0..3
    const int lane = tid & 31;
    const int g    = lane >> 2;            // 0..7
    const int q2   = (lane & 3) << 1;      // 0,2,4,6
    const int l4x2 = (lane & 3) * 2;       // uint4 index within slot row
    const u32 onehot = (q2 == 0) ? pack_h2(1.f, 0.f) : 0u;

    for (int t = blockIdx.x; t < NTILE; t += gridDim.x) {
        const int pb = t * 128 + wid * 32 + g;   // rows pb, pb+8, pb+16, pb+24

        u32 ahA[16], ahB[16];
        float D[64];

        // ====== LAYER 1 via MMA: D = [labels,1,0..] @ [W1L; b1; 0] ======
        {
            u32 lF[8];
            const uint4* Pr[4];
            #pragma unroll
            for (int rr = 0; rr < 4; rr++) {
                const int p = pb + rr * 8;
                const float2 l2 = *reinterpret_cast<const float2*>(labels + (size_t)p * 8 + q2);
                u32* lf = (rr < 2) ? lF : lF + 4;
                const int sl = rr & 1;
                lf[0 + sl] = pack_h2(l2.x, l2.y);
                lf[2 + sl] = onehot;
                Pr[rr] = reinterpret_cast<const uint4*>(g_P16 + (size_t)__ldg(&nidx[p]) * 32);
            }

            #pragma unroll
            for (int nt = 0; nt < 8; nt++) {
                float d0=0.f,d1=0.f,d2=0.f,d3=0.f,d4=0.f,d5=0.f,d6=0.f,d7=0.f;
                const uint2 b = *reinterpret_cast<const uint2*>(sBF1 + nt*64 + lane*2);
                mma16816(d0,d1,d2,d3, lF[0],lF[1],lF[2],lF[3], b.x,b.y);
                mma16816(d4,d5,d6,d7, lF[4],lF[5],lF[6],lF[7], b.x,b.y);
                D[nt*8+0]=d0; D[nt*8+1]=d1; D[nt*8+2]=d2; D[nt*8+3]=d3;
                D[nt*8+4]=d4; D[nt*8+5]=d5; D[nt*8+6]=d6; D[nt*8+7]=d7;
            }

            // h = relu(D + P16[ni]) -> A fragments (hi only)
            #pragma unroll
            for (int rr = 0; rr < 4; rr++) {
                const uint4 pa = Pr[rr][l4x2];
                const uint4 pbq = Pr[rr][l4x2 + 1];
                u32* ah = (rr < 2) ? ahA : ahB;
                const int sl = rr & 1;
                const int hb = (rr >> 1) * 4 + sl * 2;
                const u32 pk[8] = { pa.x, pa.y, pa.z, pa.w, pbq.x, pbq.y, pbq.z, pbq.w };
                #pragma unroll
                for (int nt = 0; nt < 8; nt++) {
                    const float2 pv = h2f(pk[nt]);
                    const float v0 = fmaxf(D[nt*8 + hb + 0] + pv.x, 0.f);
                    const float v1 = fmaxf(D[nt*8 + hb + 1] + pv.y, 0.f);
                    ah[(nt >> 1)*4 + (nt & 1)*2 + sl] = pack_h2(v0, v1);
                }
            }
        }

        // ================= LAYER 2: o = relu(h @ W2 + b2) =================
        gemm64x2_1t(D, ahA, ahB, sBF, lane);
        {
            u32 p01[8], p23[8], q01[8], q23[8];
            #pragma unroll
            for (int nt = 0; nt < 8; nt++) {
                const int c0 = nt * 8 + q2;
                const int kt = nt >> 1, hf = nt & 1;
                const float b0 = sB2[c0], b1 = sB2[c0 + 1];
                p01[nt] = pack_h2(fmaxf(D[nt*8+0] + b0, 0.f), fmaxf(D[nt*8+1] + b1, 0.f));
                p23[nt] = pack_h2(fmaxf(D[nt*8+2] + b0, 0.f), fmaxf(D[nt*8+3] + b1, 0.f));
                q01[nt] = pack_h2(fmaxf(D[nt*8+4] + b0, 0.f), fmaxf(D[nt*8+5] + b1, 0.f));
                q23[nt] = pack_h2(fmaxf(D[nt*8+6] + b0, 0.f), fmaxf(D[nt*8+7] + b1, 0.f));
                ahA[kt*4 + hf*2 + 0] = p01[nt];
                ahA[kt*4 + hf*2 + 1] = p23[nt];
                ahB[kt*4 + hf*2 + 0] = q01[nt];
                ahB[kt*4 + hf*2 + 1] = q23[nt];
            }
            const int slot = (lane & 3) * 8;
            uint4* r0 = reinterpret_cast<uint4*>(&g_O16[(size_t)(pb     ) * 32 + slot]);
            uint4* r1 = reinterpret_cast<uint4*>(&g_O16[(size_t)(pb +  8) * 32 + slot]);
            uint4* r2 = reinterpret_cast<uint4*>(&g_O16[(size_t)(pb + 16) * 32 + slot]);
            uint4* r3 = reinterpret_cast<uint4*>(&g_O16[(size_t)(pb + 24) * 32 + slot]);
            r0[0] = make_uint4(p01[0], p01[1], p01[2], p01[3]);
            r0[1] = make_uint4(p01[4], p01[5], p01[6], p01[7]);
            r1[0] = make_uint4(p23[0], p23[1], p23[2], p23[3]);
            r1[1] = make_uint4(p23[4], p23[5], p23[6], p23[7]);
            r2[0] = make_uint4(q01[0], q01[1], q01[2], q01[3]);
            r2[1] = make_uint4(q01[4], q01[5], q01[6], q01[7]);
            r3[0] = make_uint4(q23[0], q23[1], q23[2], q23[3]);
            r3[1] = make_uint4(q23[4], q23[5], q23[6], q23[7]);
        }

        // ===== LAYER 3: a = relu(o @ A1a + A1B[node] + b) (scores only) ===
        const uint4* G[4];
        #pragma unroll
        for (int rr = 0; rr < 4; rr++)
            G[rr] = reinterpret_cast<const uint4*>(
                g_A1B16 + (size_t)__ldg(&nodes[(pb + rr * 8) / K_N]) * 32);

        gemm64x2_1t(D, ahA, ahB, sBF + 2048, lane);
        #pragma unroll
        for (int rr = 0; rr < 4; rr++) {
            const uint4 ga = G[rr][l4x2];
            const uint4 gb = G[rr][l4x2 + 1];
            u32* ah = (rr < 2) ? ahA : ahB;
            const int sl = rr & 1;
            const int hb = (rr >> 1) * 4 + sl * 2;
            const u32 gk[8] = { ga.x, ga.y, ga.z, ga.w, gb.x, gb.y, gb.z, gb.w };
            #pragma unroll
            for (int nt = 0; nt < 8; nt++) {
                const float2 gv = h2f(gk[nt]);
                const int c0 = nt * 8 + q2;
                const float v0 = fmaxf(D[nt*8 + hb + 0] + sBa1[c0]     + gv.x, 0.f);
                const float v1 = fmaxf(D[nt*8 + hb + 1] + sBa1[c0 + 1] + gv.y, 0.f);
                ah[(nt >> 1)*4 + (nt & 1)*2 + sl] = pack_h2(v0, v1);
            }
        }

        // ========= LAYER 4: a2 = relu(a @ A2 + b); score = a2 . a3 ========
        gemm64x2_1t(D, ahA, ahB, sBF + 4096, lane);
        float s[4] = {0.f, 0.f, 0.f, 0.f};
        #pragma unroll
        for (int nt = 0; nt < 8; nt++) {
            const int c0 = nt * 8 + q2;
            const float b0 = sBa2[c0], b1 = sBa2[c0 + 1];
            const float w0 = sA3[c0],  w1 = sA3[c0 + 1];
            #pragma unroll
            for (int half = 0; half < 2; half++) {
                const float v0 = fmaxf(D[nt*8 + half*4 + 0] + b0, 0.f);
                const float v1 = fmaxf(D[nt*8 + half*4 + 1] + b1, 0.f);
                const float v2 = fmaxf(D[nt*8 + half*4 + 2] + b0, 0.f);
                const float v3 = fmaxf(D[nt*8 + half*4 + 3] + b1, 0.f);
                s[half*2]     = fmaf(v0, w0, fmaf(v1, w1, s[half*2]));
                s[half*2 + 1] = fmaf(v2, w0, fmaf(v3, w1, s[half*2 + 1]));
            }
        }
        #pragma unroll
        for (int rr = 0; rr < 4; rr++) {
            float sv = s[rr];
            sv += __shfl_xor_sync(0xffffffffu, sv, 1);
            sv += __shfl_xor_sync(0xffffffffu, sv, 2);
            if ((lane & 3) == 0) g_S[pb + rr * 8] = sv + a3b0;
        }
    }
}

// ---------------------------------------------------------------------------
// Kernel 3: masked softmax + aggregate (R12/13 proven). Column map:
// slot=lane ↔ columns (lane&7)*8 + (lane>>3)*2 + {0,1}.
// ---------------------------------------------------------------------------
__global__ void __launch_bounds__(256) k_agg(const int*   __restrict__ nodes,
                                             const int*   __restrict__ nlen,
                                             const float* __restrict__ u2e,
                                             float*       __restrict__ out)
{
    const int wid  = (blockIdx.x * 256 + threadIdx.x) >> 5;
    const int lane = threadIdx.x & 31;
    if (wid >= B_N) return;
    const int b   = wid;
    const int len = nlen[b];

    if (len <= 0) {
        const int node = nodes[b];
        const float2* src = reinterpret_cast<const float2*>(u2e + (size_t)node * 64);
        reinterpret_cast<float2*>(out + (size_t)b * 64)[lane] = src[lane];
        return;
    }

    const float* Sb = g_S + (size_t)b * K_N;
    float s0 = (lane      < len) ? Sb[lane]      : -3.0e38f;
    float s1 = (lane + 32 < len) ? Sb[lane + 32] : -3.0e38f;

    float m = fmaxf(s0, s1);
    #pragma unroll
    for (int o = 16; o > 0; o >>= 1) m = fmaxf(m, __shfl_xor_sync(0xffffffffu, m, o));

    const float e0 = (lane      < len) ? expf(s0 - m) : 0.f;
    const float e1 = (lane + 32 < len) ? expf(s1 - m) : 0.f;

    float ss = e0 + e1;
    #pragma unroll
    for (int o = 16; o > 0; o >>= 1) ss += __shfl_xor_sync(0xffffffffu, ss, o);

    const float inv = 1.f / ss;
    const float w0 = e0 * inv;
    const float w1 = e1 * inv;

    float2 agg = make_float2(0.f, 0.f);
    const u32* Ob = g_O16 + (size_t)b * K_N * 32;
    for (int k = 0; k < len; k++) {
        const float ak = (k < 32) ? __shfl_sync(0xffffffffu, w0, k)
                                  : __shfl_sync(0xffffffffu, w1, k - 32);
        const u32 ov = Ob[k * 32 + lane];
        const float2 of = h2f(ov);
        agg.x = fmaf(ak, of.x, agg.x);
        agg.y = fmaf(ak, of.y, agg.y);
    }
    const int col = (lane & 7) * 8 + (lane >> 3) * 2;
    *reinterpret_cast<float2*>(out + (size_t)b * 64 + col) = agg;
}

// ---------------------------------------------------------------------------
// kernel_launch
// ---------------------------------------------------------------------------
extern "C" void kernel_launch(void* const* d_in, const int* in_sizes, int n_in,
                              void* d_out, int out_size)
{
    const int*   nodes  = (const int*)  d_in[0];
    const int*   nidx   = (const int*)  d_in[1];
    const int*   nlen   = (const int*)  d_in[2];
    const float* labels = (const float*)d_in[3];
    const float* u2e    = (const float*)d_in[4];
    const float* w1W    = (const float*)d_in[5];
    const float* w1b    = (const float*)d_in[6];
    const float* w2W    = (const float*)d_in[7];
    const float* w2b    = (const float*)d_in[8];
    const float* a1W    = (const float*)d_in[9];
    const float* a1b    = (const float*)d_in[10];
    const float* a2W    = (const float*)d_in[11];
    const float* a2b    = (const float*)d_in[12];
    const float* a3W    = (const float*)d_in[13];
    const float* a3b    = (const float*)d_in[14];
    float* out = (float*)d_out;

    cudaFuncSetAttribute(k_main, cudaFuncAttributeMaxDynamicSharedMemorySize, DSM_BYTES);

    k_wfrag<<<21, 256>>>(w2W, a1W, a2W, w1W, w1b);
    k_pre  <<<(VTILE + 7) / 8, 256>>>(u2e);
    k_main <<<296, 128, DSM_BYTES>>>(nodes, nidx, labels,
                                     w2b, a1b, a2b, a3W, a3b);
    k_agg  <<<(B_N * 32 + 255) / 256, 256>>>(nodes, nlen, u2e, out);
}